// round 6
// baseline (speedup 1.0000x reference)
#include <cuda_runtime.h>

#define B_  128
#define T_  256
#define R_  1024
#define NU_ 256
#define BR_ (B_*R_)

// ---------------- static device scratch ----------------
// state tensors TRANSPOSED: [r][b]
__device__ float g_xh[(size_t)T_*BR_];    // [t][r][b]
__device__ float g_xt[(size_t)T_*BR_];    // [t][r][b]
__device__ float g_hist[(size_t)T_*BR_];  // [t][r][b]
__device__ float g_sA[BR_];
__device__ float g_sB[BR_];
__device__ float g_s0[BR_];               // stays zero

typedef unsigned long long u64;

__device__ __forceinline__ u64 pk2(float lo, float hi) {
    u64 r; asm("mov.b64 %0, {%1, %2};" : "=l"(r) : "f"(lo), "f"(hi)); return r;
}
__device__ __forceinline__ void up2(float &lo, float &hi, u64 v) {
    asm("mov.b64 {%0, %1}, %2;" : "=f"(lo), "=f"(hi) : "l"(v));
}
__device__ __forceinline__ void fma2(u64 &d, u64 a, u64 b) {
    asm("fma.rn.f32x2 %0, %1, %2, %0;" : "+l"(d) : "l"(a), "l"(b));
}
__device__ __forceinline__ u64 add2(u64 a, u64 b) {
    u64 r; asm("add.rn.f32x2 %0, %1, %2;" : "=l"(r) : "l"(a), "l"(b)); return r;
}

__device__ __forceinline__ float sigmoid_(float x) {
    return __frcp_rn(1.f + __expf(-x));
}
__device__ __forceinline__ float tanh_(float x) {
    return __fmaf_rn(2.f, __frcp_rn(1.f + __expf(-2.f*x)), -1.f);
}

__device__ __forceinline__ void cp16(unsigned s, const void* g) {
    asm volatile("cp.async.cg.shared.global [%0], [%1], 16;" :: "r"(s), "l"(g));
}
__device__ __forceinline__ void cpcommit() { asm volatile("cp.async.commit_group;"); }
template<int N> __device__ __forceinline__ void cpwait() {
    asm volatile("cp.async.wait_group %0;" :: "n"(N));
}

// =================================================================================
// Stage kernel: one highway layer, tensors [r][b].
// 512 threads = 16 warps = (kq 8) x (gate 2); 4 warps/SMSP.
// Warp: full 128m x 8n tile of its gate for a 128-k eighth (thread 8m x 4n).
// Per k per thread: 2 LDS.128 (s) + 2 LDS.128 (dup'd w) + 16 FFMA2 (no mov chain).
// Weights pre-duplicated in smem (2 x 64 KB, built in prologue).
// s streamed triple-buffered: 8 eighths x 3 bufs x 4 KB = 96 KB (1 sync/chunk).
// Total dyn smem 224 KB. Reduction/tg alias the s region after the mainloop.
// =================================================================================
#define KC 8                          // k per chunk per eighth
#define NCH 16                        // chunks (128/8)
#define SM_SQ 4096
#define SM_S(q,buf)  ((((q)*3)+(buf))*SM_SQ)    // 96 KB
#define SM_WD        98304                       // + gate*65536 + k*64 + nl*8
#define SM_RED       0                           // aliases s (after mainloop)
#define SM_TG        57344                       // aliases s (after red)
#define SM_TOTAL     229376                      // 224 KB

__global__ __launch_bounds__(512, 1) void stage_kernel(
    const float* __restrict__ s_in,
    const float* __restrict__ Wh, const float* __restrict__ Wt,
    const float* __restrict__ addh, const float* __restrict__ addt,
    int per_elem,
    float* __restrict__ s_out)
{
    extern __shared__ char sm[];
    const int tid  = threadIdx.x;
    const int n0   = blockIdx.x * 8;
    const int warp = tid >> 5, lane = tid & 31;
    const int kq   = warp >> 1, gate = warp & 1;
    const int mg   = lane & 15, ng = lane >> 4;       // ng: 2 groups of 4 n
    const int mA   = mg * 4;
    const int mB   = 64 + mg * 4;
    const unsigned smb = (unsigned)__cvta_generic_to_shared(sm);

    // ---- prologue: build duplicated weight tables (both gates, 128 KB) ----
    #pragma unroll
    for (int it = 0; it < 4; ++it) {
        int idx = tid + it*512;            // 0..2047
        int k = idx >> 1, half = idx & 1;
        float4 vh = *(const float4*)(Wh + (size_t)k*R_ + n0 + half*4);
        float4 vt = *(const float4*)(Wt + (size_t)k*R_ + n0 + half*4);
        ulonglong2 h0; h0.x = pk2(vh.x, vh.x); h0.y = pk2(vh.y, vh.y);
        ulonglong2 h1; h1.x = pk2(vh.z, vh.z); h1.y = pk2(vh.w, vh.w);
        ulonglong2 t0; t0.x = pk2(vt.x, vt.x); t0.y = pk2(vt.y, vt.y);
        ulonglong2 t1; t1.x = pk2(vt.z, vt.z); t1.y = pk2(vt.w, vt.w);
        char* ph = sm + SM_WD + k*64 + half*32;
        char* pt = ph + 65536;
        *(ulonglong2*)(ph)      = h0;
        *(ulonglong2*)(ph + 16) = h1;
        *(ulonglong2*)(pt)      = t0;
        *(ulonglong2*)(pt + 16) = t1;
    }

    // ---- prologue: s chunk 0 (all 8 eighths) ----
    #pragma unroll
    for (int j = 0; j < 4; ++j) {
        int idx = tid + j*512;             // 0..2047
        int q = idx >> 8;
        int off = (idx & 255) * 16;
        cp16(smb + SM_S(q,0) + off,
             (const char*)s_in + (size_t)(q*128)*512 + off);
    }
    cpcommit();

    u64 acc[16];
    #pragma unroll
    for (int a = 0; a < 16; ++a) acc[a] = 0;

    const char* wgbase = sm + SM_WD + gate*65536 + ng*32;

    for (int c = 0; c < NCH; ++c) {
        if (c + 1 < NCH) {
            const int nb = (c+1) % 3;
            #pragma unroll
            for (int j = 0; j < 4; ++j) {
                int idx = tid + j*512;
                int q = idx >> 8;
                int off = (idx & 255) * 16;
                cp16(smb + SM_S(q,nb) + off,
                     (const char*)s_in + (size_t)(q*128 + (c+1)*KC)*512 + off);
            }
            cpcommit();
            cpwait<1>();
        } else {
            cpwait<0>();
        }
        __syncthreads();

        // ---- mainloop: 4 LDS.128 + 16 FFMA2 per k ----
        const char* sp = sm + SM_S(kq, c%3) + mg*16;
        const char* wp = wgbase + (size_t)(kq*128 + c*KC)*64;
        #pragma unroll
        for (int kl = 0; kl < KC; ++kl) {
            ulonglong2 sA = *(const ulonglong2*)(sp + kl*512);
            ulonglong2 sB = *(const ulonglong2*)(sp + kl*512 + 256);
            ulonglong2 wA = *(const ulonglong2*)(wp + kl*64);
            ulonglong2 wB = *(const ulonglong2*)(wp + kl*64 + 16);
            fma2(acc[0],  sA.x, wA.x); fma2(acc[1],  sA.y, wA.x);
            fma2(acc[2],  sB.x, wA.x); fma2(acc[3],  sB.y, wA.x);
            fma2(acc[4],  sA.x, wA.y); fma2(acc[5],  sA.y, wA.y);
            fma2(acc[6],  sB.x, wA.y); fma2(acc[7],  sB.y, wA.y);
            fma2(acc[8],  sA.x, wB.x); fma2(acc[9],  sA.y, wB.x);
            fma2(acc[10], sB.x, wB.x); fma2(acc[11], sB.y, wB.x);
            fma2(acc[12], sA.x, wB.y); fma2(acc[13], sA.y, wB.y);
            fma2(acc[14], sB.x, wB.y); fma2(acc[15], sB.y, wB.y);
        }
    }
    __syncthreads();   // protect s region before aliasing as red/tg

    // ---- cross-eighth reduction (red aliases s) ----
    u64* red = (u64*)(sm + SM_RED);
    if (kq > 0) {
        u64* dst = red + (size_t)(((kq-1)*2 + gate)*32 + lane)*16;
        #pragma unroll
        for (int a = 0; a < 16; ++a) dst[a] = acc[a];
    }
    __syncthreads();
    if (kq == 0) {
        #pragma unroll
        for (int r = 0; r < 7; ++r) {
            const u64* src = red + (size_t)((r*2 + gate)*32 + lane)*16;
            #pragma unroll
            for (int a = 0; a < 16; ++a) acc[a] = add2(acc[a], src[a]);
        }
    }

    // ---- epilogue (kq0 warps): gate1 sigmoid -> tg; gate0 combines ----
    float* tg = (float*)(sm + SM_TG);
    if (kq == 0 && gate == 1) {
        #pragma unroll
        for (int j = 0; j < 4; ++j) {
            int n = n0 + ng*4 + j;
            float v[8];
            up2(v[0], v[1], acc[j*4+0]); up2(v[2], v[3], acc[j*4+1]);
            up2(v[4], v[5], acc[j*4+2]); up2(v[6], v[7], acc[j*4+3]);
            float4 tA, tB;
            if (per_elem) {
                tA = *(const float4*)(addt + (size_t)n*128 + mA);
                tB = *(const float4*)(addt + (size_t)n*128 + mB);
            } else {
                float bv = addt[n];
                tA = make_float4(bv, bv, bv, bv); tB = tA;
            }
            float4 oA, oB;
            oA.x = sigmoid_(v[0] + tA.x); oA.y = sigmoid_(v[1] + tA.y);
            oA.z = sigmoid_(v[2] + tA.z); oA.w = sigmoid_(v[3] + tA.w);
            oB.x = sigmoid_(v[4] + tB.x); oB.y = sigmoid_(v[5] + tB.y);
            oB.z = sigmoid_(v[6] + tB.z); oB.w = sigmoid_(v[7] + tB.w);
            *(float4*)&tg[(ng*4+j)*128 + mA] = oA;
            *(float4*)&tg[(ng*4+j)*128 + mB] = oB;
        }
    }
    __syncthreads();
    if (kq == 0 && gate == 0) {
        #pragma unroll
        for (int j = 0; j < 4; ++j) {
            int n = n0 + ng*4 + j;
            float v[8];
            up2(v[0], v[1], acc[j*4+0]); up2(v[2], v[3], acc[j*4+1]);
            up2(v[4], v[5], acc[j*4+2]); up2(v[6], v[7], acc[j*4+3]);
            float4 hA, hB;
            if (per_elem) {
                hA = *(const float4*)(addh + (size_t)n*128 + mA);
                hB = *(const float4*)(addh + (size_t)n*128 + mB);
            } else {
                float bv = addh[n];
                hA = make_float4(bv, bv, bv, bv); hB = hA;
            }
            float4 tgA = *(float4*)&tg[(ng*4+j)*128 + mA];
            float4 tgB = *(float4*)&tg[(ng*4+j)*128 + mB];
            float4 svA = *(const float4*)(s_in + (size_t)n*128 + mA);
            float4 svB = *(const float4*)(s_in + (size_t)n*128 + mB);
            float4 oA, oB;
            oA.x = (tanh_(v[0] + hA.x) - svA.x) * tgA.x + svA.x;
            oA.y = (tanh_(v[1] + hA.y) - svA.y) * tgA.y + svA.y;
            oA.z = (tanh_(v[2] + hA.z) - svA.z) * tgA.z + svA.z;
            oA.w = (tanh_(v[3] + hA.w) - svA.w) * tgA.w + svA.w;
            oB.x = (tanh_(v[4] + hB.x) - svB.x) * tgB.x + svB.x;
            oB.y = (tanh_(v[5] + hB.y) - svB.y) * tgB.y + svB.y;
            oB.z = (tanh_(v[6] + hB.z) - svB.z) * tgB.z + svB.z;
            oB.w = (tanh_(v[7] + hB.w) - svB.w) * tgB.w + svB.w;
            *(float4*)(s_out + (size_t)n*128 + mA) = oA;
            *(float4*)(s_out + (size_t)n*128 + mB) = oB;
        }
    }
}

// =================================================================================
// Pre kernel: xh = emb[tok]@Wh0x + bh0 ; xt = emb[tok]@Wt0x + bt0, stored [t][r][b].
// =================================================================================
#define KBP 8
__global__ __launch_bounds__(256, 1) void pre_kernel(
    const int* __restrict__ tok, const float* __restrict__ emb,
    const float* __restrict__ Whx, const float* __restrict__ Wtx,
    const float* __restrict__ bh, const float* __restrict__ bt)
{
    __shared__ float x_sm[NU_*34];
    __shared__ u64 wh_sm[KBP*64];
    __shared__ u64 wt_sm[KBP*64];

    const int tid  = threadIdx.x;
    const int row0 = blockIdx.y * 32;
    const int n0   = blockIdx.x * 64;

    #pragma unroll
    for (int it = 0; it < 8; ++it) {
        int idx = tid + it*256;
        int r = idx >> 6, q = idx & 63;
        int rho = row0 + r;
        int b = rho & (B_-1), t = rho >> 7;
        int token = tok[b*T_ + t];
        float4 v = *(const float4*)(emb + (size_t)token*NU_ + 4*q);
        x_sm[(4*q+0)*34 + r] = v.x;
        x_sm[(4*q+1)*34 + r] = v.y;
        x_sm[(4*q+2)*34 + r] = v.z;
        x_sm[(4*q+3)*34 + r] = v.w;
    }
    __syncthreads();

    const int mp = tid & 15;
    const int ng = tid >> 4;
    u64 acch[4] = {0,0,0,0};
    u64 acct[4] = {0,0,0,0};

    for (int k0 = 0; k0 < NU_; k0 += KBP) {
        #pragma unroll
        for (int it = 0; it < 2; ++it) {
            int idx = tid + it*256;
            int kl = idx >> 6, c = idx & 63;
            float wh = Whx[(size_t)(k0+kl)*R_ + n0 + c];
            float wt = Wtx[(size_t)(k0+kl)*R_ + n0 + c];
            wh_sm[kl*64 + c] = pk2(wh, wh);
            wt_sm[kl*64 + c] = pk2(wt, wt);
        }
        __syncthreads();
        #pragma unroll
        for (int kl = 0; kl < KBP; ++kl) {
            u64 x2 = *(const u64*)&x_sm[(k0+kl)*34 + 2*mp];
            ulonglong2 wa = *(const ulonglong2*)&wh_sm[kl*64 + 4*ng];
            ulonglong2 wb = *(const ulonglong2*)&wh_sm[kl*64 + 4*ng + 2];
            ulonglong2 ta = *(const ulonglong2*)&wt_sm[kl*64 + 4*ng];
            ulonglong2 tb = *(const ulonglong2*)&wt_sm[kl*64 + 4*ng + 2];
            fma2(acch[0], x2, wa.x); fma2(acch[1], x2, wa.y);
            fma2(acch[2], x2, wb.x); fma2(acch[3], x2, wb.y);
            fma2(acct[0], x2, ta.x); fma2(acct[1], x2, ta.y);
            fma2(acct[2], x2, tb.x); fma2(acct[3], x2, tb.y);
        }
        __syncthreads();
    }

    #pragma unroll
    for (int j = 0; j < 4; ++j) {
        int n = n0 + 4*ng + j;
        float lo, hi, tlo, thi;
        up2(lo, hi, acch[j]);
        up2(tlo, thi, acct[j]);
        int rho = row0 + 2*mp;
        int b = rho & (B_-1), t = rho >> 7;
        size_t base = (size_t)t*BR_ + (size_t)n*128 + b;
        g_xh[base]   = lo  + bh[n];
        g_xh[base+1] = hi  + bh[n];
        g_xt[base]   = tlo + bt[n];
        g_xt[base+1] = thi + bt[n];
    }
}

// =================================================================================
// Post kernel: out[(b*T+t), n] = sum_k hist[t][k][b] * Wp[k][n] + bp[n].
// =================================================================================
#define KBQ 32
__global__ __launch_bounds__(256, 1) void post_kernel(
    const float* __restrict__ Wp, const float* __restrict__ bp,
    float* __restrict__ out)
{
    __shared__ float s_sm[KBQ*32];
    __shared__ u64 w_sm[KBQ*64];

    const int tid = threadIdx.x;
    const int n0  = blockIdx.x * 64;
    const int b0  = blockIdx.y * 32;
    const int t   = blockIdx.z;
    const float* A = g_hist + (size_t)t*BR_;

    const int mp = tid & 15;
    const int ng = tid >> 4;
    u64 acc[4] = {0,0,0,0};

    for (int k0 = 0; k0 < R_; k0 += KBQ) {
        {
            int kl = tid >> 3, bl = (tid & 7) * 4;
            float4 v = *(const float4*)(A + (size_t)(k0+kl)*128 + b0 + bl);
            *(float4*)&s_sm[kl*32 + bl] = v;
        }
        #pragma unroll
        for (int it = 0; it < 4; ++it) {
            int idx = tid + it*256;
            int kl = idx >> 5, c = idx & 31;
            float2 wv = *(const float2*)(Wp + (size_t)(k0+kl)*NU_ + n0 + 2*c);
            w_sm[kl*64 + 2*c]   = pk2(wv.x, wv.x);
            w_sm[kl*64 + 2*c+1] = pk2(wv.y, wv.y);
        }
        __syncthreads();
        #pragma unroll 8
        for (int kl = 0; kl < KBQ; ++kl) {
            u64 s2 = *(const u64*)&s_sm[kl*32 + 2*mp];
            ulonglong2 wa = *(const ulonglong2*)&w_sm[kl*64 + 4*ng];
            ulonglong2 wb = *(const ulonglong2*)&w_sm[kl*64 + 4*ng + 2];
            fma2(acc[0], s2, wa.x); fma2(acc[1], s2, wa.y);
            fma2(acc[2], s2, wb.x); fma2(acc[3], s2, wb.y);
        }
        __syncthreads();
    }

    #pragma unroll
    for (int j = 0; j < 4; ++j) {
        int n = n0 + 4*ng + j;
        float lo, hi;
        up2(lo, hi, acc[j]);
        int bl = b0 + 2*mp;
        out[(size_t)(bl*T_ + t)*NU_ + n]     = lo + bp[n];
        out[(size_t)((bl+1)*T_ + t)*NU_ + n] = hi + bp[n];
    }
}

// =================================================================================
extern "C" void kernel_launch(void* const* d_in, const int* in_sizes, int n_in,
                              void* d_out, int out_size) {
    const int*   tok  = (const int*)  d_in[0];
    const float* emb  = (const float*)d_in[1];
    const float* Wh0x = (const float*)d_in[2];
    const float* Wh0s = (const float*)d_in[3];
    const float* bh0  = (const float*)d_in[4];
    const float* Wt0x = (const float*)d_in[5];
    const float* Wt0s = (const float*)d_in[6];
    const float* bt0  = (const float*)d_in[7];
    const float* Whh  = (const float*)d_in[8];
    const float* bhh  = (const float*)d_in[9];
    const float* Wth  = (const float*)d_in[10];
    const float* bth  = (const float*)d_in[11];
    const float* Wp   = (const float*)d_in[12];
    const float* bp   = (const float*)d_in[13];

    float *xh, *xt, *hist, *sA, *sB, *s0;
    cudaGetSymbolAddress((void**)&xh,   g_xh);
    cudaGetSymbolAddress((void**)&xt,   g_xt);
    cudaGetSymbolAddress((void**)&hist, g_hist);
    cudaGetSymbolAddress((void**)&sA,   g_sA);
    cudaGetSymbolAddress((void**)&sB,   g_sB);
    cudaGetSymbolAddress((void**)&s0,   g_s0);

    cudaFuncSetAttribute(stage_kernel,
                         cudaFuncAttributeMaxDynamicSharedMemorySize, SM_TOTAL);

    pre_kernel<<<dim3(16, 1024), 256>>>(tok, emb, Wh0x, Wt0x, bh0, bt0);

    const float* sprev = s0;
    for (int t = 0; t < T_; ++t) {
        stage_kernel<<<128, 512, SM_TOTAL>>>(sprev, Wh0s, Wt0s,
                                             xh + (size_t)t*BR_, xt + (size_t)t*BR_,
                                             1, sA);
        stage_kernel<<<128, 512, SM_TOTAL>>>(sA, Whh, Wth, bhh, bth, 0, sB);
        stage_kernel<<<128, 512, SM_TOTAL>>>(sB, Whh + (size_t)R_*R_, Wth + (size_t)R_*R_,
                                             bhh + R_, bth + R_, 0,
                                             hist + (size_t)t*BR_);
        sprev = hist + (size_t)t*BR_;
    }

    post_kernel<<<dim3(4, 4, 256), 256>>>(Wp, bp, (float*)d_out);
}